// round 1
// baseline (speedup 1.0000x reference)
#include <cuda_runtime.h>

#define CHUNKS 16
#define RES_DIM 8192
#define NSE 1342177

// Kernel 1: initialize accumulator (d_out) with proj_vars.
// 131072 floats = 32768 float4, both pointers 16B-aligned.
__global__ void ptd_init_kernel(const float* __restrict__ proj, float* __restrict__ out) {
    int i = blockIdx.x * blockDim.x + threadIdx.x;
    if (i < (CHUNKS * RES_DIM) / 4) {
        reinterpret_cast<float4*>(out)[i] =
            reinterpret_cast<const float4*>(proj)[i];
    }
}

// Kernel 2: COO scatter.  out[chunk][row] += val * state[chunk][col]
// Grid: (blocks_x, CHUNKS). Grid-stride loop, manually unrolled x4 so the
// 12 loads of a batch issue before the 4 atomics (MLP), atomics are
// fire-and-forget (RED.E.ADD.F32, no return dependency).
__global__ void ptd_scatter_kernel(const float* __restrict__ vals,
                                   const int*   __restrict__ rows,
                                   const int*   __restrict__ cols,
                                   const float* __restrict__ state,
                                   float*       __restrict__ out) {
    const int chunk = blockIdx.y;
    const size_t base = (size_t)chunk * NSE;
    const float* __restrict__ v = vals + base;
    const int*   __restrict__ r = rows + base;
    const int*   __restrict__ c = cols + base;
    const float* __restrict__ s = state + chunk * RES_DIM;
    float* o = out + chunk * RES_DIM;

    const int stride = blockDim.x * gridDim.x;
    int i = blockIdx.x * blockDim.x + threadIdx.x;

    for (; i + 3 * stride < NSE; i += 4 * stride) {
        const int i1 = i + stride, i2 = i + 2 * stride, i3 = i + 3 * stride;
        // batch loads first (independent -> deep MLP)
        float v0 = v[i],  v1 = v[i1], v2 = v[i2], v3 = v[i3];
        int   c0 = c[i],  c1 = c[i1], c2 = c[i2], c3 = c[i3];
        int   r0 = r[i],  r1 = r[i1], r2 = r[i2], r3 = r[i3];
        float f0 = v0 * __ldg(s + c0);
        float f1 = v1 * __ldg(s + c1);
        float f2 = v2 * __ldg(s + c2);
        float f3 = v3 * __ldg(s + c3);
        atomicAdd(o + r0, f0);
        atomicAdd(o + r1, f1);
        atomicAdd(o + r2, f2);
        atomicAdd(o + r3, f3);
    }
    for (; i < NSE; i += stride) {
        atomicAdd(o + r[i], v[i] * __ldg(s + c[i]));
    }
}

// Kernel 3: in-place Horner evaluation of the degree-5 Taylor expansion of
// tanh(BIAS + z).  Coefficients computed in f32 exactly mirroring the
// reference formulas (cost is a handful of ops per thread, negligible).
__global__ void ptd_horner_kernel(float* __restrict__ out) {
    int i = blockIdx.x * blockDim.x + threadIdx.x;
    if (i >= CHUNKS * RES_DIM) return;

    const float t  = tanhf(1.6f);
    const float t2 = t * t;
    const float t3 = t2 * t;
    const float t4 = t2 * t2;
    const float t6 = t4 * t2;
    const float c0 = t;
    const float c1 = 1.0f - t2;
    const float c2 = t3 - t;
    const float c3 = -t4 + (4.0f / 3.0f) * t2 - (1.0f / 3.0f);
    const float c4 = (t / 3.0f) * (3.0f * t4 - 5.0f * t2 + 2.0f);
    const float c5 = -t6 + 2.0f * t4 - (17.0f / 15.0f) * t2 + (2.0f / 15.0f);

    float z = out[i];            // z = spmv + proj (already accumulated)
    float p = c5;
    p = fmaf(z, p, c4);
    p = fmaf(z, p, c3);
    p = fmaf(z, p, c2);
    p = fmaf(z, p, c1);
    p = fmaf(z, p, c0);
    out[i] = p;
}

extern "C" void kernel_launch(void* const* d_in, const int* in_sizes, int n_in,
                              void* d_out, int out_size) {
    const float* proj  = (const float*)d_in[0];   // (CHUNKS, RES_DIM) f32
    const float* state = (const float*)d_in[1];   // (CHUNKS, RES_DIM) f32
    const float* vals  = (const float*)d_in[2];   // (CHUNKS, NSE) f32
    const int*   rows  = (const int*)d_in[3];     // (CHUNKS, NSE) i32
    const int*   cols  = (const int*)d_in[4];     // (CHUNKS, NSE) i32
    float* out = (float*)d_out;                   // (CHUNKS, RES_DIM) f32

    // 1. out = proj
    {
        int n4 = (CHUNKS * RES_DIM) / 4;
        ptd_init_kernel<<<(n4 + 255) / 256, 256>>>(proj, out);
    }
    // 2. out += spmv  (atomic scatter)
    {
        dim3 grid(96, CHUNKS);   // 1536 blocks, ~55 nnz per thread
        ptd_scatter_kernel<<<grid, 256>>>(vals, rows, cols, state, out);
    }
    // 3. out = taylor_tanh(out)
    {
        int n = CHUNKS * RES_DIM;
        ptd_horner_kernel<<<(n + 255) / 256, 256>>>(out);
    }
}

// round 2
// speedup vs baseline: 1.0530x; 1.0530x over previous
#include <cuda_runtime.h>

#define CHUNKS 16
#define RES_DIM 8192
#define NSE 1342177

// Kernel 1: out = proj  (vectorized copy; out is the accumulator)
__global__ void ptd_init_kernel(const float* __restrict__ proj, float* __restrict__ out) {
    int i = blockIdx.x * blockDim.x + threadIdx.x;
    if (i < (CHUNKS * RES_DIM) / 4) {
        reinterpret_cast<float4*>(out)[i] =
            reinterpret_cast<const float4*>(proj)[i];
    }
}

// Kernel 2: COO scatter with shared-memory-staged state and float4/int4
// streaming loads. out[chunk][row] += val * state_smem[col].
// Per-chunk base = chunk*NSE is not 16B aligned (NSE odd), so each chunk has
// a <=3-element scalar head and tail handled by block (0, chunk).
__global__ void __launch_bounds__(256)
ptd_scatter_kernel(const float* __restrict__ vals,
                   const int*   __restrict__ rows,
                   const int*   __restrict__ cols,
                   const float* __restrict__ state,
                   float*       __restrict__ out) {
    __shared__ float s[RES_DIM];               // 32 KB per-chunk state copy

    const int chunk = blockIdx.y;
    const size_t base = (size_t)chunk * NSE;
    float* __restrict__ o = out + chunk * RES_DIM;

    // Stage state[chunk] into shared memory (vectorized: 2048 float4).
    {
        const float4* st4 = reinterpret_cast<const float4*>(state + (size_t)chunk * RES_DIM);
        float4* sh4 = reinterpret_cast<float4*>(s);
        #pragma unroll
        for (int i = threadIdx.x; i < RES_DIM / 4; i += 256) sh4[i] = st4[i];
    }
    __syncthreads();

    // Alignment split: head scalars until 16B-aligned, then nvec float4, then tail.
    const int head = (int)((4 - (base & 3)) & 3);
    const int nvec = (NSE - head) >> 2;
    const int tail = NSE - head - (nvec << 2);

    const float4* __restrict__ v4 = reinterpret_cast<const float4*>(vals + base + head);
    const int4*   __restrict__ r4 = reinterpret_cast<const int4*>(rows + base + head);
    const int4*   __restrict__ c4 = reinterpret_cast<const int4*>(cols + base + head);

    const int stride = blockDim.x * gridDim.x;
    int i = blockIdx.x * blockDim.x + threadIdx.x;

    // Main loop, unrolled x2 for MLP: issue 6 LDG.128 before any RED.
    for (; i + stride < nvec; i += 2 * stride) {
        const int j = i + stride;
        float4 va = v4[i]; float4 vb = v4[j];
        int4   ca = c4[i]; int4   cb = c4[j];
        int4   ra = r4[i]; int4   rb = r4[j];

        float fa0 = va.x * s[ca.x], fa1 = va.y * s[ca.y];
        float fa2 = va.z * s[ca.z], fa3 = va.w * s[ca.w];
        float fb0 = vb.x * s[cb.x], fb1 = vb.y * s[cb.y];
        float fb2 = vb.z * s[cb.z], fb3 = vb.w * s[cb.w];

        atomicAdd(o + ra.x, fa0);
        atomicAdd(o + ra.y, fa1);
        atomicAdd(o + ra.z, fa2);
        atomicAdd(o + ra.w, fa3);
        atomicAdd(o + rb.x, fb0);
        atomicAdd(o + rb.y, fb1);
        atomicAdd(o + rb.z, fb2);
        atomicAdd(o + rb.w, fb3);
    }
    for (; i < nvec; i += stride) {
        float4 va = v4[i];
        int4   ca = c4[i];
        int4   ra = r4[i];
        atomicAdd(o + ra.x, va.x * s[ca.x]);
        atomicAdd(o + ra.y, va.y * s[ca.y]);
        atomicAdd(o + ra.z, va.z * s[ca.z]);
        atomicAdd(o + ra.w, va.w * s[ca.w]);
    }

    // Head + tail scalars (block x==0 only).
    if (blockIdx.x == 0) {
        if (threadIdx.x < head) {
            const size_t k = base + threadIdx.x;
            atomicAdd(o + rows[k], vals[k] * s[cols[k]]);
        }
        if (threadIdx.x >= 32 && threadIdx.x < 32 + tail) {
            const size_t k = base + head + ((size_t)nvec << 2) + (threadIdx.x - 32);
            atomicAdd(o + rows[k], vals[k] * s[cols[k]]);
        }
    }
}

// Kernel 3: in-place Horner evaluation of degree-5 Taylor of tanh(1.6 + z).
__global__ void ptd_horner_kernel(float* __restrict__ out) {
    int i = blockIdx.x * blockDim.x + threadIdx.x;
    if (i >= (CHUNKS * RES_DIM) / 4) return;

    const float t  = tanhf(1.6f);
    const float t2 = t * t;
    const float t3 = t2 * t;
    const float t4 = t2 * t2;
    const float t6 = t4 * t2;
    const float c0 = t;
    const float c1 = 1.0f - t2;
    const float c2 = t3 - t;
    const float c3 = -t4 + (4.0f / 3.0f) * t2 - (1.0f / 3.0f);
    const float c4 = (t / 3.0f) * (3.0f * t4 - 5.0f * t2 + 2.0f);
    const float c5 = -t6 + 2.0f * t4 - (17.0f / 15.0f) * t2 + (2.0f / 15.0f);

    float4 z = reinterpret_cast<float4*>(out)[i];
    float4 p;
    p.x = fmaf(z.x, fmaf(z.x, fmaf(z.x, fmaf(z.x, fmaf(z.x, c5, c4), c3), c2), c1), c0);
    p.y = fmaf(z.y, fmaf(z.y, fmaf(z.y, fmaf(z.y, fmaf(z.y, c5, c4), c3), c2), c1), c0);
    p.z = fmaf(z.z, fmaf(z.z, fmaf(z.z, fmaf(z.z, fmaf(z.z, c5, c4), c3), c2), c1), c0);
    p.w = fmaf(z.w, fmaf(z.w, fmaf(z.w, fmaf(z.w, fmaf(z.w, c5, c4), c3), c2), c1), c0);
    reinterpret_cast<float4*>(out)[i] = p;
}

extern "C" void kernel_launch(void* const* d_in, const int* in_sizes, int n_in,
                              void* d_out, int out_size) {
    const float* proj  = (const float*)d_in[0];
    const float* state = (const float*)d_in[1];
    const float* vals  = (const float*)d_in[2];
    const int*   rows  = (const int*)d_in[3];
    const int*   cols  = (const int*)d_in[4];
    float* out = (float*)d_out;

    {
        int n4 = (CHUNKS * RES_DIM) / 4;
        ptd_init_kernel<<<(n4 + 255) / 256, 256>>>(proj, out);
    }
    {
        // 64 x 16 = 1024 blocks; 32KB smem/block -> ~6-7 blocks/SM resident.
        dim3 grid(64, CHUNKS);
        ptd_scatter_kernel<<<grid, 256>>>(vals, rows, cols, state, out);
    }
    {
        int n4 = (CHUNKS * RES_DIM) / 4;
        ptd_horner_kernel<<<(n4 + 255) / 256, 256>>>(out);
    }
}

// round 3
// speedup vs baseline: 1.0790x; 1.0248x over previous
#include <cuda_runtime.h>

#define CHUNKS 16
#define RES_DIM 8192
#define NSE 1342177

// Second accumulator (device scratch; allocation-free per harness rules).
__device__ float g_acc1[CHUNKS * RES_DIM];

// Kernel 1: out = proj, g_acc1 = 0.   (32768 float4 each)
__global__ void ptd_init_kernel(const float* __restrict__ proj, float* __restrict__ out) {
    int i = blockIdx.x * blockDim.x + threadIdx.x;
    if (i < (CHUNKS * RES_DIM) / 4) {
        reinterpret_cast<float4*>(out)[i] = reinterpret_cast<const float4*>(proj)[i];
        reinterpret_cast<float4*>(g_acc1)[i] = make_float4(0.f, 0.f, 0.f, 0.f);
    }
}

// Kernel 2: COO scatter.
//  - state staged in shared memory (32 KB)
//  - vals/rows/cols streamed with __ldcs (evict-first: keeps accumulators L2-resident)
//  - atomics alternate between two accumulators (halves per-address contention)
__global__ void __launch_bounds__(512)
ptd_scatter_kernel(const float* __restrict__ vals,
                   const int*   __restrict__ rows,
                   const int*   __restrict__ cols,
                   const float* __restrict__ state,
                   float*       __restrict__ out) {
    __shared__ float s[RES_DIM];

    const int chunk = blockIdx.y;
    const size_t base = (size_t)chunk * NSE;
    float* __restrict__ o0 = out + chunk * RES_DIM;
    float* __restrict__ o1 = g_acc1 + chunk * RES_DIM;

    // Stage state[chunk] into shared memory.
    {
        const float4* st4 = reinterpret_cast<const float4*>(state + (size_t)chunk * RES_DIM);
        float4* sh4 = reinterpret_cast<float4*>(s);
        #pragma unroll
        for (int i = threadIdx.x; i < RES_DIM / 4; i += 512) sh4[i] = st4[i];
    }
    __syncthreads();

    // Alignment split (base not 16B-aligned since NSE is odd).
    const int head = (int)((4 - (base & 3)) & 3);
    const int nvec = (NSE - head) >> 2;
    const int tail = NSE - head - (nvec << 2);

    const float4* __restrict__ v4 = reinterpret_cast<const float4*>(vals + base + head);
    const int4*   __restrict__ r4 = reinterpret_cast<const int4*>(rows + base + head);
    const int4*   __restrict__ c4 = reinterpret_cast<const int4*>(cols + base + head);

    const int stride = blockDim.x * gridDim.x;
    int i = blockIdx.x * blockDim.x + threadIdx.x;

    // Main loop, unrolled x2 (8 nnz/thread/iter): 6 streaming LDG.128 up front,
    // then 8 REDs split across the two accumulators.
    for (; i + stride < nvec; i += 2 * stride) {
        const int j = i + stride;
        float4 va = __ldcs(v4 + i); float4 vb = __ldcs(v4 + j);
        int4   ca = __ldcs(c4 + i); int4   cb = __ldcs(c4 + j);
        int4   ra = __ldcs(r4 + i); int4   rb = __ldcs(r4 + j);

        float fa0 = va.x * s[ca.x], fa1 = va.y * s[ca.y];
        float fa2 = va.z * s[ca.z], fa3 = va.w * s[ca.w];
        float fb0 = vb.x * s[cb.x], fb1 = vb.y * s[cb.y];
        float fb2 = vb.z * s[cb.z], fb3 = vb.w * s[cb.w];

        atomicAdd(o0 + ra.x, fa0);
        atomicAdd(o1 + ra.y, fa1);
        atomicAdd(o0 + ra.z, fa2);
        atomicAdd(o1 + ra.w, fa3);
        atomicAdd(o0 + rb.x, fb0);
        atomicAdd(o1 + rb.y, fb1);
        atomicAdd(o0 + rb.z, fb2);
        atomicAdd(o1 + rb.w, fb3);
    }
    for (; i < nvec; i += stride) {
        float4 va = __ldcs(v4 + i);
        int4   ca = __ldcs(c4 + i);
        int4   ra = __ldcs(r4 + i);
        atomicAdd(o0 + ra.x, va.x * s[ca.x]);
        atomicAdd(o1 + ra.y, va.y * s[ca.y]);
        atomicAdd(o0 + ra.z, va.z * s[ca.z]);
        atomicAdd(o1 + ra.w, va.w * s[ca.w]);
    }

    // Head + tail scalars (block x==0 only).
    if (blockIdx.x == 0) {
        if (threadIdx.x < head) {
            const size_t k = base + threadIdx.x;
            atomicAdd(o0 + rows[k], vals[k] * s[cols[k]]);
        }
        if (threadIdx.x >= 32 && threadIdx.x < 32 + tail) {
            const size_t k = base + head + ((size_t)nvec << 2) + (threadIdx.x - 32);
            atomicAdd(o0 + rows[k], vals[k] * s[cols[k]]);
        }
    }
}

// Kernel 3: out = taylor_tanh(out + g_acc1), vectorized.
__global__ void ptd_horner_kernel(float* __restrict__ out) {
    int i = blockIdx.x * blockDim.x + threadIdx.x;
    if (i >= (CHUNKS * RES_DIM) / 4) return;

    const float t  = tanhf(1.6f);
    const float t2 = t * t;
    const float t3 = t2 * t;
    const float t4 = t2 * t2;
    const float t6 = t4 * t2;
    const float c0 = t;
    const float c1 = 1.0f - t2;
    const float c2 = t3 - t;
    const float c3 = -t4 + (4.0f / 3.0f) * t2 - (1.0f / 3.0f);
    const float c4 = (t / 3.0f) * (3.0f * t4 - 5.0f * t2 + 2.0f);
    const float c5 = -t6 + 2.0f * t4 - (17.0f / 15.0f) * t2 + (2.0f / 15.0f);

    float4 a = reinterpret_cast<float4*>(out)[i];
    float4 b = reinterpret_cast<const float4*>(g_acc1)[i];
    float zx = a.x + b.x, zy = a.y + b.y, zz = a.z + b.z, zw = a.w + b.w;
    float4 p;
    p.x = fmaf(zx, fmaf(zx, fmaf(zx, fmaf(zx, fmaf(zx, c5, c4), c3), c2), c1), c0);
    p.y = fmaf(zy, fmaf(zy, fmaf(zy, fmaf(zy, fmaf(zy, c5, c4), c3), c2), c1), c0);
    p.z = fmaf(zz, fmaf(zz, fmaf(zz, fmaf(zz, fmaf(zz, c5, c4), c3), c2), c1), c0);
    p.w = fmaf(zw, fmaf(zw, fmaf(zw, fmaf(zw, fmaf(zw, c5, c4), c3), c2), c1), c0);
    reinterpret_cast<float4*>(out)[i] = p;
}

extern "C" void kernel_launch(void* const* d_in, const int* in_sizes, int n_in,
                              void* d_out, int out_size) {
    const float* proj  = (const float*)d_in[0];
    const float* state = (const float*)d_in[1];
    const float* vals  = (const float*)d_in[2];
    const int*   rows  = (const int*)d_in[3];
    const int*   cols  = (const int*)d_in[4];
    float* out = (float*)d_out;

    {
        int n4 = (CHUNKS * RES_DIM) / 4;
        ptd_init_kernel<<<(n4 + 255) / 256, 256>>>(proj, out);
    }
    {
        dim3 grid(64, CHUNKS);   // 1024 blocks x 512 threads
        ptd_scatter_kernel<<<grid, 512>>>(vals, rows, cols, state, out);
    }
    {
        int n4 = (CHUNKS * RES_DIM) / 4;
        ptd_horner_kernel<<<(n4 + 255) / 256, 256>>>(out);
    }
}